// round 1
// baseline (speedup 1.0000x reference)
#include <cuda_runtime.h>
#include <cstdint>

// Problem constants (from reference)
#define H        256
#define FOURH    1024
#define NG       2048     // num graphs
#define APG      64       // atoms per graph
#define TOTAL    (NG*APG)

// ---------------- device scratch (no allocations allowed) ----------------
__device__ float g_Wc[FOURH * H];      // W_ih + W_hh   [1024,256]
__device__ float g_bc[FOURH];          // b_ih + b_hh
__device__ float g_q [NG * H];         // LSTM output q
__device__ float g_c [NG * H];         // LSTM cell state
__device__ float g_h [NG * H];         // h (= r of previous step)
__device__ float g_gates[NG * FOURH];  // GEMM output

// ---------------- prep: fold the two weight matrices / biases ----------------
__global__ void prep_kernel(const float* __restrict__ W_ih,
                            const float* __restrict__ W_hh,
                            const float* __restrict__ b_ih,
                            const float* __restrict__ b_hh) {
    int idx = blockIdx.x * 256 + threadIdx.x;
    if (idx < FOURH * H) g_Wc[idx] = W_ih[idx] + W_hh[idx];
    if (idx < FOURH)     g_bc[idx] = b_ih[idx] + b_hh[idx];
}

// ---------------- step 0: h = 0 -> gates = bc, broadcast q0/c0 ----------------
__global__ void step0_qc_kernel() {
    int b = blockIdx.x;
    int j = threadIdx.x;           // 0..255
    float gi = g_bc[j];
    float gg = g_bc[512 + j];
    float go = g_bc[768 + j];
    float si = 1.0f / (1.0f + expf(-gi));
    float so = 1.0f / (1.0f + expf(-go));
    float c  = si * tanhf(gg);     // f*c_old term is zero
    float q  = so * tanhf(c);
    g_c[b * H + j] = c;
    g_q[b * H + j] = q;
}

// ---------------- GEMM: gates = h @ Wc^T  ([2048,256] x [256,1024]) ----------------
// BM=64, BN=64, BK=16, 256 threads, 4x4 microtile per thread.
__global__ void gemm_gates_kernel() {
    __shared__ float As[16][64];   // As[k][m]
    __shared__ float Bs[16][64];   // Bs[k][n] = Wc[n][k]
    int tid = threadIdx.x;
    int tx  = tid & 15;            // n group
    int ty  = tid >> 4;            // m group
    int mb  = blockIdx.y * 64;
    int nb  = blockIdx.x * 64;

    int lr = tid >> 2;             // 0..63 row within tile
    int lc = tid & 3;              // float4 index along k

    float acc[4][4] = {};

    for (int kk = 0; kk < H; kk += 16) {
        float4 av = *(const float4*)&g_h [(mb + lr) * H + kk + lc * 4];
        float4 bv = *(const float4*)&g_Wc[(nb + lr) * H + kk + lc * 4];
        As[lc*4+0][lr] = av.x; As[lc*4+1][lr] = av.y;
        As[lc*4+2][lr] = av.z; As[lc*4+3][lr] = av.w;
        Bs[lc*4+0][lr] = bv.x; Bs[lc*4+1][lr] = bv.y;
        Bs[lc*4+2][lr] = bv.z; Bs[lc*4+3][lr] = bv.w;
        __syncthreads();
        #pragma unroll
        for (int k = 0; k < 16; ++k) {
            float4 a4 = *(const float4*)&As[k][ty * 4];
            float4 b4 = *(const float4*)&Bs[k][tx * 4];
            float a[4] = {a4.x, a4.y, a4.z, a4.w};
            float bb[4] = {b4.x, b4.y, b4.z, b4.w};
            #pragma unroll
            for (int i = 0; i < 4; ++i)
                #pragma unroll
                for (int j = 0; j < 4; ++j)
                    acc[i][j] = fmaf(a[i], bb[j], acc[i][j]);
        }
        __syncthreads();
    }
    #pragma unroll
    for (int i = 0; i < 4; ++i) {
        float4 v = make_float4(acc[i][0], acc[i][1], acc[i][2], acc[i][3]);
        *(float4*)&g_gates[(size_t)(mb + ty * 4 + i) * FOURH + nb + tx * 4] = v;
    }
}

// ---------------- pointwise LSTM: gates -> (q, c) ----------------
__global__ void lstm_pointwise_kernel(float* __restrict__ out_q /* may be null */) {
    int b = blockIdx.x;
    int j = threadIdx.x;
    const float* grow = g_gates + (size_t)b * FOURH;
    float gi = grow[j]        + g_bc[j];
    float gf = grow[256 + j]  + g_bc[256 + j];
    float gg = grow[512 + j]  + g_bc[512 + j];
    float go = grow[768 + j]  + g_bc[768 + j];
    float si = 1.0f / (1.0f + expf(-gi));
    float sf = 1.0f / (1.0f + expf(-gf));
    float so = 1.0f / (1.0f + expf(-go));
    float c  = sf * g_c[b * H + j] + si * tanhf(gg);
    float q  = so * tanhf(c);
    g_c[b * H + j] = c;
    g_q[b * H + j] = q;
    if (out_q) out_q[(size_t)b * (2 * H) + j] = q;
}

// ---------------- fused attention: scores -> softmax -> weighted sum ----------------
// One CTA per graph. X tile (64x256 f32 = 64KB) staged in dynamic SMEM once.
#define ATT_SMEM ((APG * H + H + APG) * sizeof(float))

__global__ void attention_kernel(const float* __restrict__ x,
                                 float* __restrict__ r_out /* may be null */) {
    extern __shared__ float sm[];
    float* Xs = sm;                 // [64][256]
    float* qs = sm + APG * H;       // [256]
    float* sc = qs + H;             // [64]

    int b   = blockIdx.x;
    int tid = threadIdx.x;

    // load X tile (coalesced float4), 16 float4 per thread
    const float4* xg = (const float4*)(x + (size_t)b * APG * H);
    float4* Xs4 = (float4*)Xs;
    #pragma unroll
    for (int i = 0; i < (APG * H / 4) / 256; ++i)
        Xs4[tid + i * 256] = xg[tid + i * 256];
    qs[tid] = g_q[b * H + tid];
    __syncthreads();

    // scores: warp w handles atoms [w*8, w*8+8); conflict-free SMEM access
    int w = tid >> 5, lane = tid & 31;
    #pragma unroll
    for (int aa = 0; aa < 8; ++aa) {
        int a = w * 8 + aa;
        const float* xr = Xs + a * H;
        float p = 0.0f;
        #pragma unroll
        for (int k = 0; k < 8; ++k)
            p = fmaf(xr[lane + 32 * k], qs[lane + 32 * k], p);
        #pragma unroll
        for (int off = 16; off; off >>= 1)
            p += __shfl_xor_sync(0xffffffffu, p, off);
        if (lane == 0) sc[a] = p;
    }
    __syncthreads();

    // softmax over 64 scores (warp 0)
    if (w == 0) {
        float v0 = sc[lane], v1 = sc[lane + 32];
        float mx = fmaxf(v0, v1);
        #pragma unroll
        for (int off = 16; off; off >>= 1)
            mx = fmaxf(mx, __shfl_xor_sync(0xffffffffu, mx, off));
        float e0 = expf(v0 - mx), e1 = expf(v1 - mx);
        float s = e0 + e1;
        #pragma unroll
        for (int off = 16; off; off >>= 1)
            s += __shfl_xor_sync(0xffffffffu, s, off);
        float inv = 1.0f / s;
        sc[lane]      = e0 * inv;
        sc[lane + 32] = e1 * inv;
    }
    __syncthreads();

    // weighted sum: thread j computes r[j]
    float r = 0.0f;
    #pragma unroll 16
    for (int a = 0; a < APG; ++a)
        r = fmaf(sc[a], Xs[a * H + tid], r);
    g_h[b * H + tid] = r;
    if (r_out) r_out[(size_t)b * (2 * H) + H + tid] = r;
}

// ---------------- launch ----------------
extern "C" void kernel_launch(void* const* d_in, const int* in_sizes, int n_in,
                              void* d_out, int out_size) {
    const float* x    = (const float*)d_in[0];
    // d_in[1] = batch (int64), d_in[2] = sizes (int64): structure is fixed
    // (atom a belongs to graph a/64), so these are not needed.
    const float* W_ih = (const float*)d_in[3];
    const float* W_hh = (const float*)d_in[4];
    const float* b_ih = (const float*)d_in[5];
    const float* b_hh = (const float*)d_in[6];
    float* out = (float*)d_out;

    cudaFuncSetAttribute(attention_kernel,
                         cudaFuncAttributeMaxDynamicSharedMemorySize,
                         (int)ATT_SMEM);

    prep_kernel<<<1024, 256>>>(W_ih, W_hh, b_ih, b_hh);

    // step 0: gates from bias only (h = 0)
    step0_qc_kernel<<<NG, 256>>>();
    attention_kernel<<<NG, 256, ATT_SMEM>>>(x, nullptr);

    // step 1
    gemm_gates_kernel<<<dim3(FOURH / 64, NG / 64), 256>>>();
    lstm_pointwise_kernel<<<NG, 256>>>(nullptr);
    attention_kernel<<<NG, 256, ATT_SMEM>>>(x, nullptr);

    // step 2 (final): q -> out[:, 0:H], r -> out[:, H:2H]
    gemm_gates_kernel<<<dim3(FOURH / 64, NG / 64), 256>>>();
    lstm_pointwise_kernel<<<NG, 256>>>(out);
    attention_kernel<<<NG, 256, ATT_SMEM>>>(x, out);
}

// round 2
// speedup vs baseline: 1.2426x; 1.2426x over previous
#include <cuda_runtime.h>
#include <cstdint>

#define H        256
#define FOURH    1024
#define NG       2048
#define APG      64
#define GRIDA    148          // persistent attention grid
#define TILE_B   (APG*H*4)    // 65536 bytes per graph tile

// ---------------- device scratch ----------------
__device__ float g_Wc[FOURH * H];      // W_ih + W_hh
__device__ float g_bc[FOURH];          // b_ih + b_hh
__device__ float g_q0[H];              // step-0 q (graph-invariant)
__device__ float g_c0[H];              // step-0 c (graph-invariant)
__device__ float g_c [NG * H];         // per-graph cell state (after step1)
__device__ float g_h [NG * H];         // h = r of previous step
__device__ float g_gates[NG * FOURH];  // GEMM output (raw, no bias)

__device__ __forceinline__ float sigmoidf_(float v) {
    return 1.0f / (1.0f + __expf(-v));
}

// ---------------- prep ----------------
__global__ void prep_kernel(const float* __restrict__ W_ih,
                            const float* __restrict__ W_hh,
                            const float* __restrict__ b_ih,
                            const float* __restrict__ b_hh) {
    int idx = blockIdx.x * 256 + threadIdx.x;
    if (idx < FOURH * H) g_Wc[idx] = W_ih[idx] + W_hh[idx];
    if (idx < FOURH)     g_bc[idx] = b_ih[idx] + b_hh[idx];
    if (idx < H) {
        // h=0, c=0: gates = b_ih + b_hh
        float gi = b_ih[idx]       + b_hh[idx];
        float gg = b_ih[512 + idx] + b_hh[512 + idx];
        float go = b_ih[768 + idx] + b_hh[768 + idx];
        float c  = sigmoidf_(gi) * tanhf(gg);
        g_c0[idx] = c;
        g_q0[idx] = sigmoidf_(go) * tanhf(c);
    }
}

// ---------------- packed f32x2 helpers ----------------
__device__ __forceinline__ unsigned long long pack2(float lo, float hi) {
    unsigned long long r;
    asm("mov.b64 %0, {%1, %2};" : "=l"(r) : "f"(lo), "f"(hi));
    return r;
}
__device__ __forceinline__ void ffma2(unsigned long long& d,
                                      unsigned long long a,
                                      unsigned long long b) {
    asm("fma.rn.f32x2 %0, %1, %2, %0;" : "+l"(d) : "l"(a), "l"(b));
}

// ---------------- GEMM: gates = h @ Wc^T, f32x2 packed FMA ----------------
// BM=128, BN=64, BK=16, 256 threads, microtile 8m(4 pairs) x 4n per thread.
__global__ void __launch_bounds__(256) gemm_gates_kernel() {
    __shared__ float As[2][16][128];   // As[k][m]
    __shared__ float Bs[2][16][64];    // Bs[k][n]

    int tid = threadIdx.x;
    int tx  = tid & 15;                // n group: cols tx*4..+3
    int ty  = tid >> 4;                // m group: rows ty*8..+7
    int mb  = blockIdx.y * 128;
    int nb  = blockIdx.x * 64;

    // load indices: A slab = 512 float4 (2/thread), B slab = 256 float4 (1/thread)
    int a_r0 = tid >> 2,  a_k = tid & 3;            // f4 idx tid
    int a_r1 = (tid + 256) >> 2;                    // f4 idx tid+256 (same a_k pattern)
    int b_r  = tid >> 2,  b_k = tid & 3;

    unsigned long long acc[4][4];
    #pragma unroll
    for (int p = 0; p < 4; ++p)
        #pragma unroll
        for (int j = 0; j < 4; ++j) acc[p][j] = 0ull;

    float4 av0, av1, bv;
    // prologue: load slab 0
    av0 = *(const float4*)&g_h [(size_t)(mb + a_r0) * H + a_k * 4];
    av1 = *(const float4*)&g_h [(size_t)(mb + a_r1) * H + a_k * 4];
    bv  = *(const float4*)&g_Wc[(size_t)(nb + b_r ) * H + b_k * 4];
    {
        int buf = 0;
        As[buf][a_k*4+0][a_r0] = av0.x; As[buf][a_k*4+1][a_r0] = av0.y;
        As[buf][a_k*4+2][a_r0] = av0.z; As[buf][a_k*4+3][a_r0] = av0.w;
        As[buf][a_k*4+0][a_r1] = av1.x; As[buf][a_k*4+1][a_r1] = av1.y;
        As[buf][a_k*4+2][a_r1] = av1.z; As[buf][a_k*4+3][a_r1] = av1.w;
        Bs[buf][b_k*4+0][b_r]  = bv.x;  Bs[buf][b_k*4+1][b_r]  = bv.y;
        Bs[buf][b_k*4+2][b_r]  = bv.z;  Bs[buf][b_k*4+3][b_r]  = bv.w;
    }
    __syncthreads();

    const int NS = H / 16;   // 16 slabs
    for (int s = 0; s < NS; ++s) {
        int buf = s & 1;
        if (s + 1 < NS) {
            int kk = (s + 1) * 16;
            av0 = *(const float4*)&g_h [(size_t)(mb + a_r0) * H + kk + a_k * 4];
            av1 = *(const float4*)&g_h [(size_t)(mb + a_r1) * H + kk + a_k * 4];
            bv  = *(const float4*)&g_Wc[(size_t)(nb + b_r ) * H + kk + b_k * 4];
        }
        #pragma unroll
        for (int k = 0; k < 16; ++k) {
            unsigned long long a2[4];
            #pragma unroll
            for (int p = 0; p < 4; ++p)
                a2[p] = *(const unsigned long long*)&As[buf][k][ty * 8 + 2 * p];
            float4 b4 = *(const float4*)&Bs[buf][k][tx * 4];
            unsigned long long b2[4];
            b2[0] = pack2(b4.x, b4.x); b2[1] = pack2(b4.y, b4.y);
            b2[2] = pack2(b4.z, b4.z); b2[3] = pack2(b4.w, b4.w);
            #pragma unroll
            for (int p = 0; p < 4; ++p)
                #pragma unroll
                for (int j = 0; j < 4; ++j)
                    ffma2(acc[p][j], a2[p], b2[j]);
        }
        if (s + 1 < NS) {
            int nbuf = 1 - buf;
            As[nbuf][a_k*4+0][a_r0] = av0.x; As[nbuf][a_k*4+1][a_r0] = av0.y;
            As[nbuf][a_k*4+2][a_r0] = av0.z; As[nbuf][a_k*4+3][a_r0] = av0.w;
            As[nbuf][a_k*4+0][a_r1] = av1.x; As[nbuf][a_k*4+1][a_r1] = av1.y;
            As[nbuf][a_k*4+2][a_r1] = av1.z; As[nbuf][a_k*4+3][a_r1] = av1.w;
            Bs[nbuf][b_k*4+0][b_r]  = bv.x;  Bs[nbuf][b_k*4+1][b_r]  = bv.y;
            Bs[nbuf][b_k*4+2][b_r]  = bv.z;  Bs[nbuf][b_k*4+3][b_r]  = bv.w;
        }
        __syncthreads();
    }

    // epilogue: unpack pairs (lo = even m row, hi = odd m row)
    #pragma unroll
    for (int p = 0; p < 4; ++p) {
        float lo[4], hi[4];
        #pragma unroll
        for (int j = 0; j < 4; ++j) {
            union { unsigned long long u; float2 f; } cv;
            cv.u = acc[p][j];
            lo[j] = cv.f.x; hi[j] = cv.f.y;
        }
        int m0 = mb + ty * 8 + 2 * p;
        *(float4*)&g_gates[(size_t)m0       * FOURH + nb + tx * 4] =
            make_float4(lo[0], lo[1], lo[2], lo[3]);
        *(float4*)&g_gates[(size_t)(m0 + 1) * FOURH + nb + tx * 4] =
            make_float4(hi[0], hi[1], hi[2], hi[3]);
    }
}

// ---------------- persistent fused attention ----------------
// mode 0: q = g_q0 (broadcast);           r -> g_h
// mode 1: q,c from gates & g_c0; c->g_c;  r -> g_h
// mode 2: q,c from gates & g_c; q -> out; r -> out
//
// SMEM: 2 x 64KB x tiles (double buffered via cp.async.bulk + mbarrier),
//       qs[256], sc[64], red[512], mbar[2]
#define ATT_FLOATS (2*APG*H + H + APG + 512)
#define ATT_SMEM   (ATT_FLOATS*4 + 16)

__global__ void __launch_bounds__(512) attn_kernel(const float* __restrict__ x,
                                                   float* __restrict__ out,
                                                   int mode) {
    extern __shared__ __align__(16) unsigned char smraw[];
    float* xs  = (float*)smraw;              // [2][16384]
    float* qs  = xs + 2 * APG * H;           // [256]
    float* sc  = qs + H;                     // [64]
    float* red = sc + APG;                   // [512]
    // mbarriers right after (8B aligned)
    uint32_t smem_base;
    asm("{ .reg .u64 t; cvta.to.shared.u64 t, %1; cvt.u32.u64 %0, t; }"
        : "=r"(smem_base) : "l"(smraw));
    uint32_t mbar0 = smem_base + ATT_FLOATS * 4;
    uint32_t mbar1 = mbar0 + 8;
    uint32_t xs_sm0 = smem_base;
    uint32_t xs_sm1 = smem_base + APG * H * 4;

    int tid  = threadIdx.x;
    int lane = tid & 31;
    int w    = tid >> 5;

    if (tid == 0) {
        asm volatile("mbarrier.init.shared.b64 [%0], 1;" :: "r"(mbar0) : "memory");
        asm volatile("mbarrier.init.shared.b64 [%0], 1;" :: "r"(mbar1) : "memory");
    }
    __syncthreads();

    int first = blockIdx.x;
    // prologue prefetch: graph `first` into buf0
    if (first < NG && tid == 0) {
        asm volatile("mbarrier.arrive.expect_tx.shared.b64 _, [%0], %1;"
                     :: "r"(mbar0), "r"(TILE_B) : "memory");
        asm volatile("cp.async.bulk.shared::cta.global.mbarrier::complete_tx::bytes "
                     "[%0], [%1], %2, [%3];"
                     :: "r"(xs_sm0), "l"(x + (size_t)first * APG * H),
                        "r"(TILE_B), "r"(mbar0) : "memory");
    }

    int ph0 = 0, ph1 = 0;
    int i = 0;
    for (int b = first; b < NG; b += GRIDA, ++i) {
        int cur = i & 1;
        // prefetch next graph's tile into the other buffer
        int nxt = b + GRIDA;
        if (nxt < NG && tid == 0) {
            uint32_t mb_n = cur ? mbar0 : mbar1;
            uint32_t xs_n = cur ? xs_sm0 : xs_sm1;
            asm volatile("mbarrier.arrive.expect_tx.shared.b64 _, [%0], %1;"
                         :: "r"(mb_n), "r"(TILE_B) : "memory");
            asm volatile("cp.async.bulk.shared::cta.global.mbarrier::complete_tx::bytes "
                         "[%0], [%1], %2, [%3];"
                         :: "r"(xs_n), "l"(x + (size_t)nxt * APG * H),
                            "r"(TILE_B), "r"(mb_n) : "memory");
        }

        // ---- fused LSTM pointwise: compute q into qs ----
        if (tid < H) {
            int j = tid;
            float q;
            if (mode == 0) {
                q = g_q0[j];
            } else {
                const float* gr = g_gates + (size_t)b * FOURH;
                float gi = gr[j]       + g_bc[j];
                float gf = gr[256 + j] + g_bc[256 + j];
                float gg = gr[512 + j] + g_bc[512 + j];
                float go = gr[768 + j] + g_bc[768 + j];
                float cp = (mode == 1) ? g_c0[j] : g_c[(size_t)b * H + j];
                float c  = sigmoidf_(gf) * cp + sigmoidf_(gi) * tanhf(gg);
                q = sigmoidf_(go) * tanhf(c);
                if (mode == 1) g_c[(size_t)b * H + j] = c;
                if (mode == 2) out[(size_t)b * (2 * H) + j] = q;
            }
            qs[j] = q;
        }

        // ---- wait for current tile ----
        {
            uint32_t mb_c = cur ? mbar1 : mbar0;
            int ph = cur ? ph1 : ph0;
            uint32_t done;
            do {
                asm volatile(
                    "{ .reg .pred p; "
                    "mbarrier.try_wait.parity.acquire.cta.shared::cta.b64 p, [%1], %2, 0x989680; "
                    "selp.b32 %0, 1, 0, p; }"
                    : "=r"(done) : "r"(mb_c), "r"(ph) : "memory");
            } while (!done);
            if (cur) ph1 ^= 1; else ph0 ^= 1;
        }
        __syncthreads();   // tile + qs visible to all

        const float* X = xs + cur * APG * H;

        // ---- scores: 16 warps x 4 atoms ----
        float qreg[8];
        #pragma unroll
        for (int k = 0; k < 8; ++k) qreg[k] = qs[lane + 32 * k];
        #pragma unroll
        for (int aa = 0; aa < 4; ++aa) {
            int a = w * 4 + aa;
            const float* xr = X + a * H;
            float p = 0.0f;
            #pragma unroll
            for (int k = 0; k < 8; ++k)
                p = fmaf(xr[lane + 32 * k], qreg[k], p);
            #pragma unroll
            for (int off = 16; off; off >>= 1)
                p += __shfl_xor_sync(0xffffffffu, p, off);
            if (lane == 0) sc[a] = p;
        }
        __syncthreads();

        // ---- softmax over 64 (warp 0) ----
        if (w == 0) {
            float v0 = sc[lane], v1 = sc[lane + 32];
            float mx = fmaxf(v0, v1);
            #pragma unroll
            for (int off = 16; off; off >>= 1)
                mx = fmaxf(mx, __shfl_xor_sync(0xffffffffu, mx, off));
            float e0 = __expf(v0 - mx), e1 = __expf(v1 - mx);
            float s = e0 + e1;
            #pragma unroll
            for (int off = 16; off; off >>= 1)
                s += __shfl_xor_sync(0xffffffffu, s, off);
            float inv = 1.0f / s;
            sc[lane]      = e0 * inv;
            sc[lane + 32] = e1 * inv;
        }
        __syncthreads();

        // ---- weighted sum: 512 threads, 2 halves of atoms ----
        {
            int j    = tid & (H - 1);
            int half = tid >> 8;
            const float* Xh = X + half * 32 * H;
            float r = 0.0f;
            #pragma unroll
            for (int a0 = 0; a0 < 32; ++a0)
                r = fmaf(sc[half * 32 + a0], Xh[a0 * H + j], r);
            red[tid] = r;
        }
        __syncthreads();
        if (tid < H) {
            float rr = red[tid] + red[tid + H];
            g_h[(size_t)b * H + tid] = rr;
            if (mode == 2) out[(size_t)b * (2 * H) + H + tid] = rr;
        }
        __syncthreads();   // buffer `cur` free for the prefetch 2 iters ahead
    }
}

// ---------------- launch ----------------
extern "C" void kernel_launch(void* const* d_in, const int* in_sizes, int n_in,
                              void* d_out, int out_size) {
    const float* x    = (const float*)d_in[0];
    const float* W_ih = (const float*)d_in[3];
    const float* W_hh = (const float*)d_in[4];
    const float* b_ih = (const float*)d_in[5];
    const float* b_hh = (const float*)d_in[6];
    float* out = (float*)d_out;

    cudaFuncSetAttribute(attn_kernel,
                         cudaFuncAttributeMaxDynamicSharedMemorySize,
                         (int)ATT_SMEM);

    prep_kernel<<<1024, 256>>>(W_ih, W_hh, b_ih, b_hh);

    dim3 ggrid(FOURH / 64, NG / 128);

    attn_kernel<<<GRIDA, 512, ATT_SMEM>>>(x, nullptr, 0);   // step 0
    gemm_gates_kernel<<<ggrid, 256>>>();
    attn_kernel<<<GRIDA, 512, ATT_SMEM>>>(x, nullptr, 1);   // step 1
    gemm_gates_kernel<<<ggrid, 256>>>();
    attn_kernel<<<GRIDA, 512, ATT_SMEM>>>(x, out, 2);       // step 2
}

// round 3
// speedup vs baseline: 1.3856x; 1.1151x over previous
#include <cuda_runtime.h>
#include <cstdint>

#define H        256
#define FOURH    1024
#define NG       2048
#define APG      64
#define GRIDA    296          // 2 CTAs per SM (148 SMs)
#define TILE_B   (APG*H*4)    // 65536 bytes per graph tile

// ---------------- device scratch ----------------
__device__ float g_Wc[FOURH * H];      // W_ih + W_hh
__device__ float g_bc[FOURH];          // b_ih + b_hh
__device__ float g_q0[H];              // step-0 q (graph-invariant)
__device__ float g_c0[H];              // step-0 c (graph-invariant)
__device__ float g_c [NG * H];         // per-graph cell state (after step1)
__device__ float g_h [NG * H];         // h = r of previous step
__device__ float g_gates[NG * FOURH];  // GEMM output (raw, no bias)

__device__ __forceinline__ float sigmoidf_(float v) {
    return 1.0f / (1.0f + __expf(-v));
}

// ---------------- prep ----------------
__global__ void prep_kernel(const float* __restrict__ W_ih,
                            const float* __restrict__ W_hh,
                            const float* __restrict__ b_ih,
                            const float* __restrict__ b_hh) {
    int idx = blockIdx.x * 256 + threadIdx.x;
    if (idx < FOURH * H) g_Wc[idx] = W_ih[idx] + W_hh[idx];
    if (idx < FOURH)     g_bc[idx] = b_ih[idx] + b_hh[idx];
    if (idx < H) {
        float gi = b_ih[idx]       + b_hh[idx];
        float gg = b_ih[512 + idx] + b_hh[512 + idx];
        float go = b_ih[768 + idx] + b_hh[768 + idx];
        float c  = sigmoidf_(gi) * tanhf(gg);
        g_c0[idx] = c;
        g_q0[idx] = sigmoidf_(go) * tanhf(c);
    }
}

// ---------------- packed f32x2 helpers ----------------
__device__ __forceinline__ unsigned long long pack2(float lo, float hi) {
    unsigned long long r;
    asm("mov.b64 %0, {%1, %2};" : "=l"(r) : "f"(lo), "f"(hi));
    return r;
}
__device__ __forceinline__ void ffma2(unsigned long long& d,
                                      unsigned long long a,
                                      unsigned long long b) {
    asm("fma.rn.f32x2 %0, %1, %2, %0;" : "+l"(d) : "l"(a), "l"(b));
}

// ---------------- GEMM: gates = h @ Wc^T, f32x2 packed FMA ----------------
// BM=128, BN=64, BK=16, 256 threads, microtile 8m(4 pairs) x 4n per thread.
__global__ void __launch_bounds__(256) gemm_gates_kernel() {
    __shared__ float As[2][16][128];   // As[k][m]
    __shared__ float Bs[2][16][64];    // Bs[k][n]

    int tid = threadIdx.x;
    int tx  = tid & 15;
    int ty  = tid >> 4;
    int mb  = blockIdx.y * 128;
    int nb  = blockIdx.x * 64;

    int a_r0 = tid >> 2,  a_k = tid & 3;
    int a_r1 = (tid + 256) >> 2;
    int b_r  = tid >> 2,  b_k = tid & 3;

    unsigned long long acc[4][4];
    #pragma unroll
    for (int p = 0; p < 4; ++p)
        #pragma unroll
        for (int j = 0; j < 4; ++j) acc[p][j] = 0ull;

    float4 av0, av1, bv;
    av0 = *(const float4*)&g_h [(size_t)(mb + a_r0) * H + a_k * 4];
    av1 = *(const float4*)&g_h [(size_t)(mb + a_r1) * H + a_k * 4];
    bv  = *(const float4*)&g_Wc[(size_t)(nb + b_r ) * H + b_k * 4];
    {
        int buf = 0;
        As[buf][a_k*4+0][a_r0] = av0.x; As[buf][a_k*4+1][a_r0] = av0.y;
        As[buf][a_k*4+2][a_r0] = av0.z; As[buf][a_k*4+3][a_r0] = av0.w;
        As[buf][a_k*4+0][a_r1] = av1.x; As[buf][a_k*4+1][a_r1] = av1.y;
        As[buf][a_k*4+2][a_r1] = av1.z; As[buf][a_k*4+3][a_r1] = av1.w;
        Bs[buf][b_k*4+0][b_r]  = bv.x;  Bs[buf][b_k*4+1][b_r]  = bv.y;
        Bs[buf][b_k*4+2][b_r]  = bv.z;  Bs[buf][b_k*4+3][b_r]  = bv.w;
    }
    __syncthreads();

    const int NS = H / 16;
    for (int s = 0; s < NS; ++s) {
        int buf = s & 1;
        if (s + 1 < NS) {
            int kk = (s + 1) * 16;
            av0 = *(const float4*)&g_h [(size_t)(mb + a_r0) * H + kk + a_k * 4];
            av1 = *(const float4*)&g_h [(size_t)(mb + a_r1) * H + kk + a_k * 4];
            bv  = *(const float4*)&g_Wc[(size_t)(nb + b_r ) * H + kk + b_k * 4];
        }
        #pragma unroll
        for (int k = 0; k < 16; ++k) {
            unsigned long long a2[4];
            #pragma unroll
            for (int p = 0; p < 4; ++p)
                a2[p] = *(const unsigned long long*)&As[buf][k][ty * 8 + 2 * p];
            float4 b4 = *(const float4*)&Bs[buf][k][tx * 4];
            unsigned long long b2[4];
            b2[0] = pack2(b4.x, b4.x); b2[1] = pack2(b4.y, b4.y);
            b2[2] = pack2(b4.z, b4.z); b2[3] = pack2(b4.w, b4.w);
            #pragma unroll
            for (int p = 0; p < 4; ++p)
                #pragma unroll
                for (int j = 0; j < 4; ++j)
                    ffma2(acc[p][j], a2[p], b2[j]);
        }
        if (s + 1 < NS) {
            int nbuf = 1 - buf;
            As[nbuf][a_k*4+0][a_r0] = av0.x; As[nbuf][a_k*4+1][a_r0] = av0.y;
            As[nbuf][a_k*4+2][a_r0] = av0.z; As[nbuf][a_k*4+3][a_r0] = av0.w;
            As[nbuf][a_k*4+0][a_r1] = av1.x; As[nbuf][a_k*4+1][a_r1] = av1.y;
            As[nbuf][a_k*4+2][a_r1] = av1.z; As[nbuf][a_k*4+3][a_r1] = av1.w;
            Bs[nbuf][b_k*4+0][b_r]  = bv.x;  Bs[nbuf][b_k*4+1][b_r]  = bv.y;
            Bs[nbuf][b_k*4+2][b_r]  = bv.z;  Bs[nbuf][b_k*4+3][b_r]  = bv.w;
        }
        __syncthreads();
    }

    #pragma unroll
    for (int p = 0; p < 4; ++p) {
        float lo[4], hi[4];
        #pragma unroll
        for (int j = 0; j < 4; ++j) {
            union { unsigned long long u; float2 f; } cv;
            cv.u = acc[p][j];
            lo[j] = cv.f.x; hi[j] = cv.f.y;
        }
        int m0 = mb + ty * 8 + 2 * p;
        *(float4*)&g_gates[(size_t)m0       * FOURH + nb + tx * 4] =
            make_float4(lo[0], lo[1], lo[2], lo[3]);
        *(float4*)&g_gates[(size_t)(m0 + 1) * FOURH + nb + tx * 4] =
            make_float4(hi[0], hi[1], hi[2], hi[3]);
    }
}

// ---------------- persistent fused attention ----------------
// 2 CTAs per SM; single 64KB tile buffer per CTA; cross-CTA overlap hides
// the TMA load. mode 0: q = q0; mode 1: q,c from gates & c0; mode 2: final.
#define ATT_FLOATS (APG*H + H + APG + 512)
#define ATT_SMEM   (ATT_FLOATS*4 + 8)

__global__ void __launch_bounds__(512) attn_kernel(const float* __restrict__ x,
                                                   float* __restrict__ out,
                                                   int mode) {
    extern __shared__ __align__(16) unsigned char smraw[];
    float* xs  = (float*)smraw;              // [64][256]
    float* qs  = xs + APG * H;               // [256]
    float* sc  = qs + H;                     // [64]
    float* red = sc + APG;                   // [512]
    uint32_t smem_base;
    asm("{ .reg .u64 t; cvta.to.shared.u64 t, %1; cvt.u32.u64 %0, t; }"
        : "=r"(smem_base) : "l"(smraw));
    uint32_t mbar  = smem_base + ATT_FLOATS * 4;
    uint32_t xs_sm = smem_base;

    int tid  = threadIdx.x;
    int lane = tid & 31;
    int w    = tid >> 5;

    if (tid == 0)
        asm volatile("mbarrier.init.shared.b64 [%0], 1;" :: "r"(mbar) : "memory");
    __syncthreads();

    int ph = 0;
    for (int b = blockIdx.x; b < NG; b += GRIDA) {
        // kick off the tile load immediately
        if (tid == 0) {
            asm volatile("mbarrier.arrive.expect_tx.shared.b64 _, [%0], %1;"
                         :: "r"(mbar), "r"(TILE_B) : "memory");
            asm volatile("cp.async.bulk.shared::cta.global.mbarrier::complete_tx::bytes "
                         "[%0], [%1], %2, [%3];"
                         :: "r"(xs_sm), "l"(x + (size_t)b * APG * H),
                            "r"(TILE_B), "r"(mbar) : "memory");
        }

        // fused LSTM pointwise -> q (overlaps TMA)
        if (tid < H) {
            int j = tid;
            float q;
            if (mode == 0) {
                q = g_q0[j];
            } else {
                const float* gr = g_gates + (size_t)b * FOURH;
                float gi = gr[j]       + g_bc[j];
                float gf = gr[256 + j] + g_bc[256 + j];
                float gg = gr[512 + j] + g_bc[512 + j];
                float go = gr[768 + j] + g_bc[768 + j];
                float cp = (mode == 1) ? g_c0[j] : g_c[(size_t)b * H + j];
                float c  = sigmoidf_(gf) * cp + sigmoidf_(gi) * tanhf(gg);
                q = sigmoidf_(go) * tanhf(c);
                if (mode == 1) g_c[(size_t)b * H + j] = c;
                if (mode == 2) out[(size_t)b * (2 * H) + j] = q;
            }
            qs[j] = q;
        }

        // wait for the tile
        {
            uint32_t done;
            do {
                asm volatile(
                    "{ .reg .pred p; "
                    "mbarrier.try_wait.parity.acquire.cta.shared::cta.b64 p, [%1], %2, 0x989680; "
                    "selp.b32 %0, 1, 0, p; }"
                    : "=r"(done) : "r"(mbar), "r"(ph) : "memory");
            } while (!done);
            ph ^= 1;
        }
        __syncthreads();

        // scores: 16 warps x 4 atoms
        float qreg[8];
        #pragma unroll
        for (int k = 0; k < 8; ++k) qreg[k] = qs[lane + 32 * k];
        #pragma unroll
        for (int aa = 0; aa < 4; ++aa) {
            int a = w * 4 + aa;
            const float* xr = xs + a * H;
            float p = 0.0f;
            #pragma unroll
            for (int k = 0; k < 8; ++k)
                p = fmaf(xr[lane + 32 * k], qreg[k], p);
            #pragma unroll
            for (int off = 16; off; off >>= 1)
                p += __shfl_xor_sync(0xffffffffu, p, off);
            if (lane == 0) sc[a] = p;
        }
        __syncthreads();

        // softmax over 64 (warp 0)
        if (w == 0) {
            float v0 = sc[lane], v1 = sc[lane + 32];
            float mx = fmaxf(v0, v1);
            #pragma unroll
            for (int off = 16; off; off >>= 1)
                mx = fmaxf(mx, __shfl_xor_sync(0xffffffffu, mx, off));
            float e0 = __expf(v0 - mx), e1 = __expf(v1 - mx);
            float s = e0 + e1;
            #pragma unroll
            for (int off = 16; off; off >>= 1)
                s += __shfl_xor_sync(0xffffffffu, s, off);
            float inv = 1.0f / s;
            sc[lane]      = e0 * inv;
            sc[lane + 32] = e1 * inv;
        }
        __syncthreads();

        // weighted sum: 512 threads, 2 halves of atoms
        {
            int j    = tid & (H - 1);
            int half = tid >> 8;
            const float* Xh = xs + half * 32 * H;
            float r = 0.0f;
            #pragma unroll
            for (int a0 = 0; a0 < 32; ++a0)
                r = fmaf(sc[half * 32 + a0], Xh[a0 * H + j], r);
            red[tid] = r;
        }
        __syncthreads();
        if (tid < H) {
            float rr = red[tid] + red[tid + H];
            g_h[(size_t)b * H + tid] = rr;
            if (mode == 2) out[(size_t)b * (2 * H) + H + tid] = rr;
        }
        __syncthreads();   // all reads of xs done before next load
    }
}

// ---------------- launch ----------------
extern "C" void kernel_launch(void* const* d_in, const int* in_sizes, int n_in,
                              void* d_out, int out_size) {
    const float* x    = (const float*)d_in[0];
    const float* W_ih = (const float*)d_in[3];
    const float* W_hh = (const float*)d_in[4];
    const float* b_ih = (const float*)d_in[5];
    const float* b_hh = (const float*)d_in[6];
    float* out = (float*)d_out;

    cudaFuncSetAttribute(attn_kernel,
                         cudaFuncAttributeMaxDynamicSharedMemorySize,
                         (int)ATT_SMEM);

    prep_kernel<<<1024, 256>>>(W_ih, W_hh, b_ih, b_hh);

    dim3 ggrid(FOURH / 64, NG / 128);

    attn_kernel<<<GRIDA, 512, ATT_SMEM>>>(x, nullptr, 0);   // step 0
    gemm_gates_kernel<<<ggrid, 256>>>();
    attn_kernel<<<GRIDA, 512, ATT_SMEM>>>(x, nullptr, 1);   // step 1
    gemm_gates_kernel<<<ggrid, 256>>>();
    attn_kernel<<<GRIDA, 512, ATT_SMEM>>>(x, out, 2);       // step 2
}